// round 9
// baseline (speedup 1.0000x reference)
#include <cuda_runtime.h>
#include <cuda_fp16.h>
#include <cstdint>

#define NN   100000
#define NE   1600000
#define DIN  128
#define DH   128
#define DOUT 64
#define NBLK 98          // ceil(NN/1024)

// -------- scratch (device globals: allocation-guard safe) --------
__device__ float  g_a1[(size_t)NN * DIN];    // (sum_neigh feat + feat)/(deg+1), fp32
__device__ __half g_feath[(size_t)NN * DIN]; // fp16 copy of feat (gather payload)
__device__ __half g_g2h[(size_t)NN * DOUT];  // h1 @ W2, fp16 (gather payload)
__device__ int    g_cnt[NN];
__device__ int    g_rs[NN + 1];
__device__ int    g_cur[NN];
__device__ int    g_eord[NE];                // src ids sorted by dst
__device__ int    g_bsum[NBLK];
__device__ int    g_boff[NBLK];

// -------- packed fp32x2 helpers --------
__device__ __forceinline__ unsigned long long pack2(float x) {
    unsigned long long r;
    asm("mov.b64 %0, {%1, %1};" : "=l"(r) : "r"(__float_as_uint(x)));
    return r;
}
__device__ __forceinline__ unsigned long long fma2(unsigned long long a,
                                                   unsigned long long b,
                                                   unsigned long long c) {
    unsigned long long d;
    asm("fma.rn.f32x2 %0, %1, %2, %3;" : "=l"(d) : "l"(a), "l"(b), "l"(c));
    return d;
}

// =================== feat -> fp16 copy ===================
__global__ void cvt_feat_kernel(const float* __restrict__ feat) {
    int stride = gridDim.x * blockDim.x;
    const float4* f4 = (const float4*)feat;
    uint2* o = (uint2*)g_feath;
    const int total = NN * DIN / 4;
    for (int i = blockIdx.x * blockDim.x + threadIdx.x; i < total; i += stride) {
        float4 v = f4[i];
        __half2 h0 = __floats2half2_rn(v.x, v.y);
        __half2 h1 = __floats2half2_rn(v.z, v.w);
        uint2 u;
        u.x = *(unsigned int*)&h0;
        u.y = *(unsigned int*)&h1;
        o[i] = u;
    }
}

// =================== CSR build ===================

__global__ void zero_cnt_kernel() {
    int i = blockIdx.x * blockDim.x + threadIdx.x;
    if (i < NN) g_cnt[i] = 0;
}

__global__ void hist_kernel(const int* __restrict__ dst) {
    int stride = gridDim.x * blockDim.x;
    for (int i = blockIdx.x * blockDim.x + threadIdx.x; i < NE; i += stride)
        atomicAdd(&g_cnt[dst[i]], 1);
}

__global__ void scan_blocksums_kernel() {
    __shared__ int ws[32];
    int t = threadIdx.x, b = blockIdx.x;
    int i = b * 1024 + t;
    int v = (i < NN) ? g_cnt[i] : 0;
    int lane = t & 31, w = t >> 5;
    int x = v;
#pragma unroll
    for (int o = 16; o > 0; o >>= 1) x += __shfl_down_sync(~0u, x, o);
    if (lane == 0) ws[w] = x;
    __syncthreads();
    if (w == 0) {
        int y = ws[lane];
#pragma unroll
        for (int o = 16; o > 0; o >>= 1) y += __shfl_down_sync(~0u, y, o);
        if (lane == 0) g_bsum[b] = y;
    }
}

__global__ void scan_top_kernel() {
    __shared__ int s[NBLK];
    int t = threadIdx.x;
    if (t < NBLK) s[t] = g_bsum[t];
    __syncthreads();
    if (t == 0) {
        int run = 0;
        for (int i = 0; i < NBLK; i++) { int v = s[i]; s[i] = run; run += v; }
        g_rs[NN] = NE;
    }
    __syncthreads();
    if (t < NBLK) g_boff[t] = s[t];
}

__global__ void scan_final_kernel() {
    __shared__ int ws[32];
    int t = threadIdx.x, b = blockIdx.x;
    int i = b * 1024 + t;
    int v = (i < NN) ? g_cnt[i] : 0;
    int lane = t & 31, w = t >> 5;
    int x = v;
#pragma unroll
    for (int o = 1; o < 32; o <<= 1) {
        int y = __shfl_up_sync(~0u, x, o);
        if (lane >= o) x += y;
    }
    if (lane == 31) ws[w] = x;
    __syncthreads();
    if (w == 0) {
        int y = ws[lane];
#pragma unroll
        for (int o = 1; o < 32; o <<= 1) {
            int z = __shfl_up_sync(~0u, y, o);
            if (lane >= o) y += z;
        }
        ws[lane] = y;
    }
    __syncthreads();
    int incl = x + (w > 0 ? ws[w - 1] : 0);
    int excl = incl - v + g_boff[b];
    if (i < NN) { g_rs[i] = excl; g_cur[i] = excl; }
}

__global__ void permute_kernel(const int* __restrict__ src,
                               const int* __restrict__ dst) {
    int stride = gridDim.x * blockDim.x;
    for (int e = blockIdx.x * blockDim.x + threadIdx.x; e < NE; e += stride) {
        int d = dst[e];
        int p = atomicAdd(&g_cur[d], 1);
        g_eord[p] = src[e];
    }
}

// =================== layer 1 aggregate: one warp per dst node ===================
// a1[n] = (feat[n] + sum_{e: dst=n} feat_h[src_e]) / (deg_n + 1)
// gather payload fp16 (256B/row), accumulate fp32, self term fp32.
__global__ void spmm1_kernel(const float* __restrict__ feat) {
    int w = (blockIdx.x * blockDim.x + threadIdx.x) >> 5;
    int lane = threadIdx.x & 31;
    if (w >= NN) return;
    int beg = g_rs[w], end = g_rs[w + 1];
    const uint2* fh = (const uint2*)g_feath;   // 4 halves per uint2; 32 uint2 per row
    float4 acc = __ldg(&((const float4*)feat)[w * 32 + lane]);  // self (fp32)
    int e = beg;
    for (; e + 4 <= end; e += 4) {
        int s0 = g_eord[e], s1 = g_eord[e + 1];
        int s2 = g_eord[e + 2], s3 = g_eord[e + 3];
        uint2 u0 = __ldg(&fh[s0 * 32 + lane]);
        uint2 u1 = __ldg(&fh[s1 * 32 + lane]);
        uint2 u2 = __ldg(&fh[s2 * 32 + lane]);
        uint2 u3 = __ldg(&fh[s3 * 32 + lane]);
#pragma unroll
        for (int j = 0; j < 4; j++) {
            uint2 u = (j == 0) ? u0 : (j == 1) ? u1 : (j == 2) ? u2 : u3;
            float2 f0 = __half22float2(*(__half2*)&u.x);
            float2 f1 = __half22float2(*(__half2*)&u.y);
            acc.x += f0.x; acc.y += f0.y; acc.z += f1.x; acc.w += f1.y;
        }
    }
    for (; e < end; e++) {
        int s = g_eord[e];
        uint2 u = __ldg(&fh[s * 32 + lane]);
        float2 f0 = __half22float2(*(__half2*)&u.x);
        float2 f1 = __half22float2(*(__half2*)&u.y);
        acc.x += f0.x; acc.y += f0.y; acc.z += f1.x; acc.w += f1.y;
    }
    float inv = 1.0f / (float)(end - beg + 1);
    acc.x *= inv; acc.y *= inv; acc.z *= inv; acc.w *= inv;
    ((float4*)g_a1)[w * 32 + lane] = acc;
}

// =================== fused GEMM: h1 = relu(a1@W1 + b1); g2h = fp16(h1@W2) =========
__global__ void gemm_fused_kernel(const float* __restrict__ W1,
                                  const float* __restrict__ b1,
                                  const float* __restrict__ W2) {
    extern __shared__ float sm[];
    float* W1s = sm;                       // 128*128
    float* W2s = sm + DIN * DH;            // 128*64
    float* xs  = W2s + DH * DOUT;          // 64*129
    const int tid = threadIdx.x;

    {   // stage W1, W2
        const float4* w4 = (const float4*)W1;
        float4* s4 = (float4*)W1s;
#pragma unroll
        for (int i = 0; i < 16; i++) s4[tid + 256 * i] = w4[tid + 256 * i];
        const float4* v4 = (const float4*)W2;
        float4* t4 = (float4*)W2s;
#pragma unroll
        for (int i = 0; i < 8; i++) t4[tid + 256 * i] = v4[tid + 256 * i];
    }
    const int m0 = blockIdx.x * 64;
    {   // stage a1 tile (already normalized, fp32)
        int nrow = tid >> 2;
        int kq = (tid & 3) << 5;
        int m = m0 + nrow;
        if (m < NN) {
            const float4* fr = (const float4*)(g_a1 + (size_t)m * DIN);
#pragma unroll
            for (int j = 0; j < 8; j++) {
                float4 v = fr[(kq >> 2) + j];
                float* p = &xs[nrow * 129 + kq + 4 * j];
                p[0] = v.x; p[1] = v.y; p[2] = v.z; p[3] = v.w;
            }
        }
    }
    __syncthreads();

    const int n = tid & 63;
    const int q = tid >> 6;
    const int m = m0 + n;

    // ---- phase 1: h1 cols q*32..q*32+31 ----
    unsigned long long acc[16];
#pragma unroll
    for (int j = 0; j < 16; j++) acc[j] = 0ull;
    {
        const float* xrow = &xs[n * 129];
#pragma unroll 2
        for (int k = 0; k < DIN; k++) {
            unsigned long long xx = pack2(xrow[k]);
            const float4* w4 = (const float4*)(W1s + k * DH + q * 32);
#pragma unroll
            for (int j = 0; j < 8; j++) {
                float4 wv = w4[j];
                unsigned long long w01, w23;
                asm("mov.b64 %0, {%1, %2};" : "=l"(w01)
                    : "r"(__float_as_uint(wv.x)), "r"(__float_as_uint(wv.y)));
                asm("mov.b64 %0, {%1, %2};" : "=l"(w23)
                    : "r"(__float_as_uint(wv.z)), "r"(__float_as_uint(wv.w)));
                acc[2 * j]     = fma2(xx, w01, acc[2 * j]);
                acc[2 * j + 1] = fma2(xx, w23, acc[2 * j + 1]);
            }
        }
    }
    __syncthreads();

    {   // bias + relu -> xs holds h1
        const float* bb = b1 + q * 32;
        float* hrow = &xs[n * 129 + q * 32];
#pragma unroll
        for (int j = 0; j < 16; j++) {
            unsigned int lo = (unsigned int)(acc[j] & 0xffffffffull);
            unsigned int hi = (unsigned int)(acc[j] >> 32);
            float f0 = __uint_as_float(lo) + bb[2 * j];
            float f1 = __uint_as_float(hi) + bb[2 * j + 1];
            hrow[2 * j]     = fmaxf(f0, 0.0f);
            hrow[2 * j + 1] = fmaxf(f1, 0.0f);
        }
    }
    __syncthreads();

    // ---- phase 2: g2 cols q*16..q*16+15, write fp16 ----
    unsigned long long acc2[8];
#pragma unroll
    for (int j = 0; j < 8; j++) acc2[j] = 0ull;
    {
        const float* xrow = &xs[n * 129];
#pragma unroll 2
        for (int k = 0; k < DH; k++) {
            unsigned long long xx = pack2(xrow[k]);
            const float4* w4 = (const float4*)(W2s + k * DOUT + q * 16);
#pragma unroll
            for (int j = 0; j < 4; j++) {
                float4 wv = w4[j];
                unsigned long long w01, w23;
                asm("mov.b64 %0, {%1, %2};" : "=l"(w01)
                    : "r"(__float_as_uint(wv.x)), "r"(__float_as_uint(wv.y)));
                asm("mov.b64 %0, {%1, %2};" : "=l"(w23)
                    : "r"(__float_as_uint(wv.z)), "r"(__float_as_uint(wv.w)));
                acc2[2 * j]     = fma2(xx, w01, acc2[2 * j]);
                acc2[2 * j + 1] = fma2(xx, w23, acc2[2 * j + 1]);
            }
        }
    }
    if (m < NN) {
        unsigned int h[8];
#pragma unroll
        for (int j = 0; j < 8; j++) {
            float f0 = __uint_as_float((unsigned int)(acc2[j] & 0xffffffffull));
            float f1 = __uint_as_float((unsigned int)(acc2[j] >> 32));
            __half2 hh = __floats2half2_rn(f0, f1);
            h[j] = *(unsigned int*)&hh;
        }
        uint4* o = (uint4*)(g_g2h + (size_t)m * DOUT + q * 16);
        o[0] = make_uint4(h[0], h[1], h[2], h[3]);
        o[1] = make_uint4(h[4], h[5], h[6], h[7]);
    }
}

// =================== layer 2 aggregate + epilogue ===================
// out[n] = (g2h[n] + sum g2h[src]) / (deg+1) + b2
__global__ void spmm2_kernel(const float* __restrict__ b2,
                             float* __restrict__ out) {
    int w = (blockIdx.x * blockDim.x + threadIdx.x) >> 5;
    int lane = threadIdx.x & 31;
    if (w >= NN) return;
    int beg = g_rs[w], end = g_rs[w + 1];
    const unsigned int* gh = (const unsigned int*)g_g2h;  // 1 half2 per lane, 32/row
    unsigned int su = gh[w * 32 + lane];                  // self
    float2 acc = __half22float2(*(__half2*)&su);
    int e = beg;
    for (; e + 4 <= end; e += 4) {
        int s0 = g_eord[e], s1 = g_eord[e + 1];
        int s2 = g_eord[e + 2], s3 = g_eord[e + 3];
        unsigned int u0 = __ldg(&gh[s0 * 32 + lane]);
        unsigned int u1 = __ldg(&gh[s1 * 32 + lane]);
        unsigned int u2 = __ldg(&gh[s2 * 32 + lane]);
        unsigned int u3 = __ldg(&gh[s3 * 32 + lane]);
        float2 f0 = __half22float2(*(__half2*)&u0);
        float2 f1 = __half22float2(*(__half2*)&u1);
        float2 f2 = __half22float2(*(__half2*)&u2);
        float2 f3 = __half22float2(*(__half2*)&u3);
        acc.x += (f0.x + f1.x) + (f2.x + f3.x);
        acc.y += (f0.y + f1.y) + (f2.y + f3.y);
    }
    for (; e < end; e++) {
        int s = g_eord[e];
        unsigned int u = __ldg(&gh[s * 32 + lane]);
        float2 f = __half22float2(*(__half2*)&u);
        acc.x += f.x; acc.y += f.y;
    }
    float inv = 1.0f / (float)(end - beg + 1);
    float2 bb = ((const float2*)b2)[lane];
    float2 r;
    r.x = acc.x * inv + bb.x;
    r.y = acc.y * inv + bb.y;
    ((float2*)out)[w * 32 + lane] = r;
}

// =================== launch ===================
extern "C" void kernel_launch(void* const* d_in, const int* in_sizes, int n_in,
                              void* d_out, int out_size) {
    const float* feat = (const float*)d_in[0];
    const float* W1   = (const float*)d_in[1];
    const float* b1   = (const float*)d_in[2];
    const float* W2   = (const float*)d_in[3];
    const float* b2   = (const float*)d_in[4];
    const int*   src  = (const int*)d_in[5];
    const int*   dst  = (const int*)d_in[6];
    float* out = (float*)d_out;

    const int smem = (DIN * DH + DH * DOUT + 64 * 129) * (int)sizeof(float); // 131,328
    cudaFuncSetAttribute(gemm_fused_kernel,
                         cudaFuncAttributeMaxDynamicSharedMemorySize, smem);

    // CSR build + fp16 feat copy
    zero_cnt_kernel<<<(NN + 255) / 256, 256>>>();
    hist_kernel<<<1024, 256>>>(dst);
    cvt_feat_kernel<<<2048, 256>>>(feat);
    scan_blocksums_kernel<<<NBLK, 1024>>>();
    scan_top_kernel<<<1, 128>>>();
    scan_final_kernel<<<NBLK, 1024>>>();
    permute_kernel<<<1024, 256>>>(src, dst);

    // layer 1 aggregate -> fused GEMMs -> layer 2 aggregate
    spmm1_kernel<<<NN / 8, 256>>>(feat);
    gemm_fused_kernel<<<(NN + 63) / 64, 256, smem>>>(W1, b1, W2);
    spmm2_kernel<<<NN / 8, 256>>>(b2, out);
}

// round 10
// speedup vs baseline: 1.6751x; 1.6751x over previous
#include <cuda_runtime.h>
#include <cuda_fp16.h>
#include <cstdint>

#define NN   100000
#define NE   1600000
#define DIN  128
#define DH   128
#define DOUT 64
#define NBLK 98          // ceil(NN/1024)

// -------- scratch (device globals: allocation-guard safe) --------
__device__ float  g_a1[(size_t)NN * DIN];                   // aggregated input, fp32
__device__ __align__(16) __half g_feath[(size_t)NN * DIN];  // fp16 feat (gather payload)
__device__ __align__(16) __half g_g2h[(size_t)NN * DOUT];   // h1 @ W2, fp16
__device__ int    g_cnt[NN];
__device__ int    g_rs[NN + 1];
__device__ int    g_cur[NN];
__device__ int    g_eord[NE];
__device__ int    g_bsum[NBLK];
__device__ int    g_boff[NBLK];

// -------- tf32 mma helpers --------
__device__ __forceinline__ float tf32r(float f) {
    unsigned r; asm("cvt.rna.tf32.f32 %0, %1;" : "=r"(r) : "f"(f));
    return __uint_as_float(r);
}
__device__ __forceinline__ void mma_tf32(float* d, const unsigned* a,
                                         const unsigned* b) {
    asm("mma.sync.aligned.m16n8k8.row.col.f32.tf32.tf32.f32 "
        "{%0,%1,%2,%3}, {%4,%5,%6,%7}, {%8,%9}, {%0,%1,%2,%3};"
        : "+f"(d[0]), "+f"(d[1]), "+f"(d[2]), "+f"(d[3])
        : "r"(a[0]), "r"(a[1]), "r"(a[2]), "r"(a[3]), "r"(b[0]), "r"(b[1]));
}

// =================== feat -> fp16 copy ===================
__global__ void cvt_feat_kernel(const float* __restrict__ feat) {
    int stride = gridDim.x * blockDim.x;
    const float4* f4 = (const float4*)feat;
    uint2* o = (uint2*)g_feath;
    const int total = NN * DIN / 4;
    for (int i = blockIdx.x * blockDim.x + threadIdx.x; i < total; i += stride) {
        float4 v = f4[i];
        __half2 h0 = __floats2half2_rn(v.x, v.y);
        __half2 h1 = __floats2half2_rn(v.z, v.w);
        uint2 u;
        u.x = *(unsigned int*)&h0;
        u.y = *(unsigned int*)&h1;
        o[i] = u;
    }
}

// =================== CSR build ===================

__global__ void zero_cnt_kernel() {
    int i = blockIdx.x * blockDim.x + threadIdx.x;
    if (i < NN) g_cnt[i] = 0;
}

__global__ void hist_kernel(const int* __restrict__ dst) {
    int stride = gridDim.x * blockDim.x;
    for (int i = blockIdx.x * blockDim.x + threadIdx.x; i < NE; i += stride)
        atomicAdd(&g_cnt[dst[i]], 1);
}

__global__ void scan_blocksums_kernel() {
    __shared__ int ws[32];
    int t = threadIdx.x, b = blockIdx.x;
    int i = b * 1024 + t;
    int v = (i < NN) ? g_cnt[i] : 0;
    int lane = t & 31, w = t >> 5;
    int x = v;
#pragma unroll
    for (int o = 16; o > 0; o >>= 1) x += __shfl_down_sync(~0u, x, o);
    if (lane == 0) ws[w] = x;
    __syncthreads();
    if (w == 0) {
        int y = ws[lane];
#pragma unroll
        for (int o = 16; o > 0; o >>= 1) y += __shfl_down_sync(~0u, y, o);
        if (lane == 0) g_bsum[b] = y;
    }
}

__global__ void scan_top_kernel() {
    __shared__ int s[NBLK];
    int t = threadIdx.x;
    if (t < NBLK) s[t] = g_bsum[t];
    __syncthreads();
    if (t == 0) {
        int run = 0;
        for (int i = 0; i < NBLK; i++) { int v = s[i]; s[i] = run; run += v; }
        g_rs[NN] = NE;
    }
    __syncthreads();
    if (t < NBLK) g_boff[t] = s[t];
}

__global__ void scan_final_kernel() {
    __shared__ int ws[32];
    int t = threadIdx.x, b = blockIdx.x;
    int i = b * 1024 + t;
    int v = (i < NN) ? g_cnt[i] : 0;
    int lane = t & 31, w = t >> 5;
    int x = v;
#pragma unroll
    for (int o = 1; o < 32; o <<= 1) {
        int y = __shfl_up_sync(~0u, x, o);
        if (lane >= o) x += y;
    }
    if (lane == 31) ws[w] = x;
    __syncthreads();
    if (w == 0) {
        int y = ws[lane];
#pragma unroll
        for (int o = 1; o < 32; o <<= 1) {
            int z = __shfl_up_sync(~0u, y, o);
            if (lane >= o) y += z;
        }
        ws[lane] = y;
    }
    __syncthreads();
    int incl = x + (w > 0 ? ws[w - 1] : 0);
    int excl = incl - v + g_boff[b];
    if (i < NN) { g_rs[i] = excl; g_cur[i] = excl; }
}

__global__ void permute_kernel(const int* __restrict__ src,
                               const int* __restrict__ dst) {
    int stride = gridDim.x * blockDim.x;
    for (int e = blockIdx.x * blockDim.x + threadIdx.x; e < NE; e += stride) {
        int d = dst[e];
        int p = atomicAdd(&g_cur[d], 1);
        g_eord[p] = src[e];
    }
}

// =================== layer 1 aggregate ===================
// One warp per node; 16 lanes x uint4 (16B) per 256B row -> 2 edges per step.
__global__ void spmm1_kernel() {
    int w = (blockIdx.x * blockDim.x + threadIdx.x) >> 5;
    int lane = threadIdx.x & 31;
    if (w >= NN) return;
    int beg = g_rs[w], end = g_rs[w + 1];
    const int half = lane >> 4;    // 0/1: which edge of the pair
    const int sub  = lane & 15;    // 16B chunk within row
    const uint4* fh = (const uint4*)g_feath;   // 16 uint4 per row

    float acc[8];
#pragma unroll
    for (int j = 0; j < 8; j++) acc[j] = 0.f;

    // self term (only on half 0 so it's counted once after the xor-reduce)
    if (half == 0) {
        uint4 u = __ldg(&fh[(size_t)w * 16 + sub]);
        float2 f0 = __half22float2(*(__half2*)&u.x);
        float2 f1 = __half22float2(*(__half2*)&u.y);
        float2 f2 = __half22float2(*(__half2*)&u.z);
        float2 f3 = __half22float2(*(__half2*)&u.w);
        acc[0] = f0.x; acc[1] = f0.y; acc[2] = f1.x; acc[3] = f1.y;
        acc[4] = f2.x; acc[5] = f2.y; acc[6] = f3.x; acc[7] = f3.y;
    }

    int e = beg;
    for (; e + 4 <= end; e += 4) {      // 4 edges per iteration (2 per half)
        int s0 = __ldg(&g_eord[e + half]);
        int s1 = __ldg(&g_eord[e + 2 + half]);
        uint4 u0 = __ldg(&fh[(size_t)s0 * 16 + sub]);
        uint4 u1 = __ldg(&fh[(size_t)s1 * 16 + sub]);
#pragma unroll
        for (int p = 0; p < 2; p++) {
            uint4 u = p ? u1 : u0;
            float2 f0 = __half22float2(*(__half2*)&u.x);
            float2 f1 = __half22float2(*(__half2*)&u.y);
            float2 f2 = __half22float2(*(__half2*)&u.z);
            float2 f3 = __half22float2(*(__half2*)&u.w);
            acc[0] += f0.x; acc[1] += f0.y; acc[2] += f1.x; acc[3] += f1.y;
            acc[4] += f2.x; acc[5] += f2.y; acc[6] += f3.x; acc[7] += f3.y;
        }
    }
    for (; e < end; e += 2) {           // tail: up to 2 edges
        int ee = e + half;
        bool v = ee < end;
        int s = v ? __ldg(&g_eord[ee]) : 0;
        uint4 u = __ldg(&fh[(size_t)s * 16 + sub]);
        if (v) {
            float2 f0 = __half22float2(*(__half2*)&u.x);
            float2 f1 = __half22float2(*(__half2*)&u.y);
            float2 f2 = __half22float2(*(__half2*)&u.z);
            float2 f3 = __half22float2(*(__half2*)&u.w);
            acc[0] += f0.x; acc[1] += f0.y; acc[2] += f1.x; acc[3] += f1.y;
            acc[4] += f2.x; acc[5] += f2.y; acc[6] += f3.x; acc[7] += f3.y;
        }
    }
    // combine the two halves
#pragma unroll
    for (int j = 0; j < 8; j++) acc[j] += __shfl_xor_sync(~0u, acc[j], 16);

    if (half == 0) {
        float inv = 1.0f / (float)(end - beg + 1);
        float4 r0 = make_float4(acc[0] * inv, acc[1] * inv, acc[2] * inv, acc[3] * inv);
        float4 r1 = make_float4(acc[4] * inv, acc[5] * inv, acc[6] * inv, acc[7] * inv);
        float4* o = (float4*)(g_a1 + (size_t)w * DIN + sub * 8);
        o[0] = r0; o[1] = r1;
    }
}

// =================== fused tf32 tensor-core GEMM ===================
// h1 = relu(a1@W1 + b1); g2h = fp16(h1@W2). 64-node tile, 256 threads (8 warps).
// smem (floats): W1s 128x136 | W2s 128x72 | b1s 128 | As/Hs 64x132
#define W1S_OFF 0
#define W2S_OFF (128 * 136)
#define B1S_OFF (W2S_OFF + 128 * 72)
#define AS_OFF  (B1S_OFF + 128)
#define SMEM_FLOATS (AS_OFF + 64 * 132)

__global__ __launch_bounds__(256, 1)
void gemm_fused_kernel(const float* __restrict__ W1,
                       const float* __restrict__ b1,
                       const float* __restrict__ W2) {
    extern __shared__ float sm[];
    float* W1s = sm + W1S_OFF;
    float* W2s = sm + W2S_OFF;
    float* b1s = sm + B1S_OFF;
    float* As  = sm + AS_OFF;     // aliased as Hs in phase 2
    const int tid = threadIdx.x;
    const int m0 = blockIdx.x * 64;

    {   // stage W1 (tf32-rounded), stride 136
        const float4* w4 = (const float4*)W1;
        float4* s4 = (float4*)W1s;
#pragma unroll
        for (int it = 0; it < 16; it++) {
            int idx = tid + 256 * it;           // 4096 float4
            int k = idx >> 5, q = idx & 31;
            float4 v = w4[idx];
            v.x = tf32r(v.x); v.y = tf32r(v.y); v.z = tf32r(v.z); v.w = tf32r(v.w);
            s4[k * 34 + q] = v;
        }
        // stage W2, stride 72
        const float4* v4 = (const float4*)W2;
        float4* t4 = (float4*)W2s;
#pragma unroll
        for (int it = 0; it < 8; it++) {
            int idx = tid + 256 * it;           // 2048 float4
            int k = idx >> 4, q = idx & 15;
            float4 v = v4[idx];
            v.x = tf32r(v.x); v.y = tf32r(v.y); v.z = tf32r(v.z); v.w = tf32r(v.w);
            t4[k * 18 + q] = v;
        }
        if (tid < 128) b1s[tid] = b1[tid];
        // stage a1 tile (tf32-rounded), stride 132
        const float4* a4 = (const float4*)g_a1;
        float4* s = (float4*)As;
#pragma unroll
        for (int it = 0; it < 8; it++) {
            int idx = tid + 256 * it;           // 2048 float4
            int nr = idx >> 5, q = idx & 31;
            int m = m0 + nr;
            float4 v = make_float4(0.f, 0.f, 0.f, 0.f);
            if (m < NN) v = a4[(size_t)m * 32 + q];
            v.x = tf32r(v.x); v.y = tf32r(v.y); v.z = tf32r(v.z); v.w = tf32r(v.w);
            s[nr * 33 + q] = v;
        }
    }
    __syncthreads();

    const int wid = tid >> 5, lane = tid & 31;
    const int wm = wid & 1;         // row block: 32 rows
    const int wn = wid >> 1;        // col block
    const int g = lane >> 2, t = lane & 3;

    // ---- phase 1: h1 = a1 @ W1 (M64 x N128 x K128) ----
    float d1[2][4][4];
#pragma unroll
    for (int im = 0; im < 2; im++)
#pragma unroll
        for (int jn = 0; jn < 4; jn++)
#pragma unroll
            for (int x = 0; x < 4; x++) d1[im][jn][x] = 0.f;

#pragma unroll 4
    for (int ks = 0; ks < 16; ks++) {
        int k0 = ks * 8;
        unsigned a[2][4];
#pragma unroll
        for (int im = 0; im < 2; im++) {
            int r0 = wm * 32 + im * 16 + g;
            a[im][0] = __float_as_uint(As[r0 * 132 + k0 + t]);
            a[im][1] = __float_as_uint(As[(r0 + 8) * 132 + k0 + t]);
            a[im][2] = __float_as_uint(As[r0 * 132 + k0 + t + 4]);
            a[im][3] = __float_as_uint(As[(r0 + 8) * 132 + k0 + t + 4]);
        }
#pragma unroll
        for (int jn = 0; jn < 4; jn++) {
            int col = wn * 32 + jn * 8 + g;
            unsigned b[2];
            b[0] = __float_as_uint(W1s[(k0 + t) * 136 + col]);
            b[1] = __float_as_uint(W1s[(k0 + t + 4) * 136 + col]);
            mma_tf32(d1[0][jn], a[0], b);
            mma_tf32(d1[1][jn], a[1], b);
        }
    }
    __syncthreads();   // everyone done reading As

    {   // bias + relu -> Hs (= As buffer)
#pragma unroll
        for (int im = 0; im < 2; im++) {
            int row = wm * 32 + im * 16 + g;
#pragma unroll
            for (int jn = 0; jn < 4; jn++) {
                int col = wn * 32 + jn * 8 + 2 * t;
                As[row * 132 + col]           = fmaxf(d1[im][jn][0] + b1s[col], 0.f);
                As[row * 132 + col + 1]       = fmaxf(d1[im][jn][1] + b1s[col + 1], 0.f);
                As[(row + 8) * 132 + col]     = fmaxf(d1[im][jn][2] + b1s[col], 0.f);
                As[(row + 8) * 132 + col + 1] = fmaxf(d1[im][jn][3] + b1s[col + 1], 0.f);
            }
        }
    }
    __syncthreads();

    // ---- phase 2: g2 = h1 @ W2 (M64 x N64 x K128) ----
    float d2[2][2][4];
#pragma unroll
    for (int im = 0; im < 2; im++)
#pragma unroll
        for (int jn = 0; jn < 2; jn++)
#pragma unroll
            for (int x = 0; x < 4; x++) d2[im][jn][x] = 0.f;

#pragma unroll 4
    for (int ks = 0; ks < 16; ks++) {
        int k0 = ks * 8;
        unsigned a[2][4];
#pragma unroll
        for (int im = 0; im < 2; im++) {
            int r0 = wm * 32 + im * 16 + g;
            a[im][0] = __float_as_uint(As[r0 * 132 + k0 + t]);
            a[im][1] = __float_as_uint(As[(r0 + 8) * 132 + k0 + t]);
            a[im][2] = __float_as_uint(As[r0 * 132 + k0 + t + 4]);
            a[im][3] = __float_as_uint(As[(r0 + 8) * 132 + k0 + t + 4]);
        }
#pragma unroll
        for (int jn = 0; jn < 2; jn++) {
            int col = wn * 16 + jn * 8 + g;
            unsigned b[2];
            b[0] = __float_as_uint(W2s[(k0 + t) * 72 + col]);
            b[1] = __float_as_uint(W2s[(k0 + t + 4) * 72 + col]);
            mma_tf32(d2[0][jn], a[0], b);
            mma_tf32(d2[1][jn], a[1], b);
        }
    }

    {   // write g2 as fp16
#pragma unroll
        for (int im = 0; im < 2; im++) {
            int row = wm * 32 + im * 16 + g;
            int m_lo = m0 + row, m_hi = m_lo + 8;
#pragma unroll
            for (int jn = 0; jn < 2; jn++) {
                int col = wn * 16 + jn * 8 + 2 * t;
                if (m_lo < NN) {
                    __half2 h = __floats2half2_rn(d2[im][jn][0], d2[im][jn][1]);
                    *(unsigned int*)(g_g2h + (size_t)m_lo * DOUT + col) =
                        *(unsigned int*)&h;
                }
                if (m_hi < NN) {
                    __half2 h = __floats2half2_rn(d2[im][jn][2], d2[im][jn][3]);
                    *(unsigned int*)(g_g2h + (size_t)m_hi * DOUT + col) =
                        *(unsigned int*)&h;
                }
            }
        }
    }
}

// =================== layer 2 aggregate + epilogue ===================
// One warp per node; 8 lanes x uint4 per 128B row -> 4 edges per step.
__global__ void spmm2_kernel(const float* __restrict__ b2,
                             float* __restrict__ out) {
    int w = (blockIdx.x * blockDim.x + threadIdx.x) >> 5;
    int lane = threadIdx.x & 31;
    if (w >= NN) return;
    int beg = g_rs[w], end = g_rs[w + 1];
    const int grp = lane >> 3;     // 0..3: edge within the quad
    const int sub = lane & 7;      // 16B chunk within row
    const uint4* gh = (const uint4*)g_g2h;     // 8 uint4 per row

    float acc[8];
#pragma unroll
    for (int j = 0; j < 8; j++) acc[j] = 0.f;

    if (grp == 0) {   // self
        uint4 u = __ldg(&gh[(size_t)w * 8 + sub]);
        float2 f0 = __half22float2(*(__half2*)&u.x);
        float2 f1 = __half22float2(*(__half2*)&u.y);
        float2 f2 = __half22float2(*(__half2*)&u.z);
        float2 f3 = __half22float2(*(__half2*)&u.w);
        acc[0] = f0.x; acc[1] = f0.y; acc[2] = f1.x; acc[3] = f1.y;
        acc[4] = f2.x; acc[5] = f2.y; acc[6] = f3.x; acc[7] = f3.y;
    }

    int e = beg;
    for (; e + 8 <= end; e += 8) {     // 8 edges per iteration (2 per group)
        int s0 = __ldg(&g_eord[e + grp]);
        int s1 = __ldg(&g_eord[e + 4 + grp]);
        uint4 u0 = __ldg(&gh[(size_t)s0 * 8 + sub]);
        uint4 u1 = __ldg(&gh[(size_t)s1 * 8 + sub]);
#pragma unroll
        for (int p = 0; p < 2; p++) {
            uint4 u = p ? u1 : u0;
            float2 f0 = __half22float2(*(__half2*)&u.x);
            float2 f1 = __half22float2(*(__half2*)&u.y);
            float2 f2 = __half22float2(*(__half2*)&u.z);
            float2 f3 = __half22float2(*(__half2*)&u.w);
            acc[0] += f0.x; acc[1] += f0.y; acc[2] += f1.x; acc[3] += f1.y;
            acc[4] += f2.x; acc[5] += f2.y; acc[6] += f3.x; acc[7] += f3.y;
        }
    }
    for (; e < end; e += 4) {          // tail: up to 4 edges
        int ee = e + grp;
        bool v = ee < end;
        int s = v ? __ldg(&g_eord[ee]) : 0;
        uint4 u = __ldg(&gh[(size_t)s * 8 + sub]);
        if (v) {
            float2 f0 = __half22float2(*(__half2*)&u.x);
            float2 f1 = __half22float2(*(__half2*)&u.y);
            float2 f2 = __half22float2(*(__half2*)&u.z);
            float2 f3 = __half22float2(*(__half2*)&u.w);
            acc[0] += f0.x; acc[1] += f0.y; acc[2] += f1.x; acc[3] += f1.y;
            acc[4] += f2.x; acc[5] += f2.y; acc[6] += f3.x; acc[7] += f3.y;
        }
    }
#pragma unroll
    for (int j = 0; j < 8; j++) acc[j] += __shfl_xor_sync(~0u, acc[j], 16);
#pragma unroll
    for (int j = 0; j < 8; j++) acc[j] += __shfl_xor_sync(~0u, acc[j], 8);

    if (grp == 0 && (lane >> 4) == 0) {   // lanes 0..7 write
        float inv = 1.0f / (float)(end - beg + 1);
        const float4* b4 = (const float4*)b2;
        float4 bb0 = b4[sub * 2], bb1 = b4[sub * 2 + 1];
        float4 r0, r1;
        r0.x = acc[0] * inv + bb0.x; r0.y = acc[1] * inv + bb0.y;
        r0.z = acc[2] * inv + bb0.z; r0.w = acc[3] * inv + bb0.w;
        r1.x = acc[4] * inv + bb1.x; r1.y = acc[5] * inv + bb1.y;
        r1.z = acc[6] * inv + bb1.z; r1.w = acc[7] * inv + bb1.w;
        float4* o = (float4*)(out + (size_t)w * DOUT + sub * 8);
        o[0] = r0; o[1] = r1;
    }
}

// =================== launch ===================
extern "C" void kernel_launch(void* const* d_in, const int* in_sizes, int n_in,
                              void* d_out, int out_size) {
    const float* feat = (const float*)d_in[0];
    const float* W1   = (const float*)d_in[1];
    const float* b1   = (const float*)d_in[2];
    const float* W2   = (const float*)d_in[3];
    const float* b2   = (const float*)d_in[4];
    const int*   src  = (const int*)d_in[5];
    const int*   dst  = (const int*)d_in[6];
    float* out = (float*)d_out;

    const int smem = SMEM_FLOATS * (int)sizeof(float);   // ~140.8 KB
    cudaFuncSetAttribute(gemm_fused_kernel,
                         cudaFuncAttributeMaxDynamicSharedMemorySize, smem);

    // CSR build + fp16 feat copy
    zero_cnt_kernel<<<(NN + 255) / 256, 256>>>();
    hist_kernel<<<1024, 256>>>(dst);
    cvt_feat_kernel<<<2048, 256>>>(feat);
    scan_blocksums_kernel<<<NBLK, 1024>>>();
    scan_top_kernel<<<1, 128>>>();
    scan_final_kernel<<<NBLK, 1024>>>();
    permute_kernel<<<1024, 256>>>(src, dst);

    // layer 1 aggregate -> fused tensor GEMMs -> layer 2 aggregate
    spmm1_kernel<<<NN / 8, 256>>>();
    gemm_fused_kernel<<<(NN + 63) / 64, 256, smem>>>(W1, b1, W2);
    spmm2_kernel<<<NN / 8, 256>>>(b2, out);
}